// round 16
// baseline (speedup 1.0000x reference)
#include <cuda_runtime.h>
#include <cuda_bf16.h>
#include <mma.h>
#include <cstdint>
#include <cstddef>

using namespace nvcuda;

#define MAXN 50000
#define MAXE 400000
#define PAD_ROWS 128
// weight-buffer regions inside d_bh16/d_bl16
#define INOFF 0            // input W splits (166*64 + 56*64 = 14208)
#define G1OFF 16384        // gat1 pack (65536)
#define G2OFF 81920        // gat2 pack (65536)
#define S1OFF 147456       // sage1 pack (98304) -> end 245760

// ---------------- persistent device scratch (padded for unguarded GEMM tail stores) ------------
__device__ float d_t0[((size_t)MAXN + PAD_ROWS) * 256];
__device__ float d_w0[((size_t)MAXN + PAD_ROWS) * 256];
__device__ float d_t1[((size_t)MAXN + PAD_ROWS) * 256];
__device__ float d_w1[((size_t)MAXN + PAD_ROWS) * 256];
__device__ float d_hs[(size_t)MAXN * 1024 + PAD_ROWS * 512];  // agg buffers / fused SAGE1 Z
__device__ float d_el[4 * (size_t)MAXN * 4];
__device__ float d_er[4 * (size_t)MAXN * 4];
__device__ float d_alv[2048];          // per-layer: +0 / +1024
__device__ float d_arv[2048];
__device__ __nv_bfloat16 d_bh16[245760];
__device__ __nv_bfloat16 d_bl16[245760];
__device__ float d_bsum[384];
__device__ float d_gbias[1024];        // per-layer: +0 / +512
__device__ int   d_cnt[4 * MAXN];
__device__ int   d_rpv[4 * (MAXN + 1)];
__device__ int   d_colv[4 * MAXE];

__device__ __forceinline__ void bf16_split(float v, __nv_bfloat16& h, __nv_bfloat16& l)
{
    h = __float2bfloat16(v);
    l = __float2bfloat16(v - __bfloat162float(h));
}

// ---------------- BF16 split tensor-core GEMM with pre-split B ----------------
template<bool VEC>
__launch_bounds__(256, 2)
__global__ void gemm_bs_kernel(const float* __restrict__ A,
                               const __nv_bfloat16* __restrict__ Bh,
                               const __nv_bfloat16* __restrict__ Bl,
                               float* __restrict__ C, const float* __restrict__ bias,
                               int M, int N, int K, int relu)
{
    constexpr int BM = 128, BN = 64, SKA = 32, SKB = 80;
    __shared__ __nv_bfloat16 Ahs[2][BM][SKA];
    __shared__ __nv_bfloat16 Als[2][BM][SKA];
    __shared__ __nv_bfloat16 Bhs[2][16][SKB];
    __shared__ __nv_bfloat16 Bls[2][16][SKB];
    __shared__ float Brep[16][BN];

    const int tid = threadIdx.x;
    const int wid = tid >> 5;
    const int wm = wid & 3, wn = wid >> 2;
    const int m0 = blockIdx.y * BM, n0 = blockIdx.x * BN;
    const int mw = wm * 32;
    const int nw = wn * 32;

    float4 ra4[2];  float ras[8];
    uint2 rbh2;     __nv_bfloat16 rbhs[4];
    uint2 rbl2;     __nv_bfloat16 rbls[4];

    auto ldA = [&](int t) {
        int k0 = t * 16;
        if (VEC) {
#pragma unroll
            for (int i = 0; i < 2; i++) {
                int idx = tid + i * 256;
                int r = idx >> 2, c4 = idx & 3;
                int gm = m0 + r;
                ra4[i] = (gm < M) ? *(const float4*)&A[(size_t)gm * K + k0 + c4 * 4]
                                  : make_float4(0.f, 0.f, 0.f, 0.f);
            }
        } else {
#pragma unroll
            for (int i = 0; i < 8; i++) {
                int idx = tid + i * 256;
                int r = idx >> 4, c = idx & 15;
                int gm = m0 + r;
                ras[i] = (gm < M && k0 + c < K) ? A[(size_t)gm * K + k0 + c] : 0.f;
            }
        }
    };
    auto stA = [&](int st) {
        if (VEC) {
#pragma unroll
            for (int i = 0; i < 2; i++) {
                int idx = tid + i * 256;
                int r = idx >> 2, c4 = idx & 3;
                float v[4] = {ra4[i].x, ra4[i].y, ra4[i].z, ra4[i].w};
#pragma unroll
                for (int j = 0; j < 4; j++) {
                    __nv_bfloat16 h, l;
                    bf16_split(v[j], h, l);
                    Ahs[st][r][c4 * 4 + j] = h;
                    Als[st][r][c4 * 4 + j] = l;
                }
            }
        } else {
#pragma unroll
            for (int i = 0; i < 8; i++) {
                int idx = tid + i * 256;
                int r = idx >> 4, c = idx & 15;
                __nv_bfloat16 h, l;
                bf16_split(ras[i], h, l);
                Ahs[st][r][c] = h;
                Als[st][r][c] = l;
            }
        }
    };
    auto ldB = [&](int t) {
        int k0 = t * 16;
        if (VEC) {
            int r = tid >> 4, c4 = tid & 15;
            rbh2 = *(const uint2*)&Bh[(size_t)(k0 + r) * N + n0 + c4 * 4];
            rbl2 = *(const uint2*)&Bl[(size_t)(k0 + r) * N + n0 + c4 * 4];
        } else {
#pragma unroll
            for (int i = 0; i < 4; i++) {
                int idx = tid + i * 256;
                int r = idx >> 6, c = idx & 63;
                bool ok = (k0 + r) < K;
                rbhs[i] = ok ? Bh[(size_t)(k0 + r) * N + n0 + c] : __float2bfloat16(0.f);
                rbls[i] = ok ? Bl[(size_t)(k0 + r) * N + n0 + c] : __float2bfloat16(0.f);
            }
        }
    };
    auto stB = [&](int st) {
        if (VEC) {
            int r = tid >> 4, c4 = tid & 15;
            *(uint2*)&Bhs[st][r][c4 * 4] = rbh2;
            *(uint2*)&Bls[st][r][c4 * 4] = rbl2;
        } else {
#pragma unroll
            for (int i = 0; i < 4; i++) {
                int idx = tid + i * 256;
                int r = idx >> 6, c = idx & 63;
                Bhs[st][r][c] = rbhs[i];
                Bls[st][r][c] = rbls[i];
            }
        }
    };

    ldA(0); ldB(0);
    stA(0); stB(0);
    if (bias) {
        for (int i = tid; i < 16 * BN; i += 256)
            Brep[i >> 6][i & 63] = bias[n0 + (i & 63)];
    }
    __syncthreads();

    wmma::fragment<wmma::accumulator, 16, 16, 16, float> cfr[2][2];
#pragma unroll
    for (int mi = 0; mi < 2; mi++)
#pragma unroll
        for (int ni = 0; ni < 2; ni++) {
            if (bias)
                wmma::load_matrix_sync(cfr[mi][ni], &Brep[0][nw + ni * 16], BN, wmma::mem_row_major);
            else
                wmma::fill_fragment(cfr[mi][ni], 0.f);
        }

    const int numK = (K + 15) >> 4;
    int cur = 0;
    for (int t = 0; t < numK; t++) {
        bool hasNext = (t + 1 < numK);
        if (hasNext) { ldA(t + 1); ldB(t + 1); }

        wmma::fragment<wmma::matrix_a, 16, 16, 16, __nv_bfloat16, wmma::row_major> fah[2], fal[2];
#pragma unroll
        for (int mi = 0; mi < 2; mi++) {
            wmma::load_matrix_sync(fah[mi], &Ahs[cur][mw + mi * 16][0], SKA);
            wmma::load_matrix_sync(fal[mi], &Als[cur][mw + mi * 16][0], SKA);
        }
#pragma unroll
        for (int ni = 0; ni < 2; ni++) {
            wmma::fragment<wmma::matrix_b, 16, 16, 16, __nv_bfloat16, wmma::row_major> fbh, fbl;
            wmma::load_matrix_sync(fbh, &Bhs[cur][0][nw + ni * 16], SKB);
            wmma::load_matrix_sync(fbl, &Bls[cur][0][nw + ni * 16], SKB);
#pragma unroll
            for (int mi = 0; mi < 2; mi++) {
                wmma::mma_sync(cfr[mi][ni], fah[mi], fbh, cfr[mi][ni]);
                wmma::mma_sync(cfr[mi][ni], fal[mi], fbh, cfr[mi][ni]);
                wmma::mma_sync(cfr[mi][ni], fah[mi], fbl, cfr[mi][ni]);
            }
        }

        if (hasNext) {
            stA(cur ^ 1); stB(cur ^ 1);
            __syncthreads();
            cur ^= 1;
        }
    }

#pragma unroll
    for (int mi = 0; mi < 2; mi++) {
        int gm = m0 + mw + mi * 16;
#pragma unroll
        for (int ni = 0; ni < 2; ni++) {
            if (relu) {
#pragma unroll
                for (int q = 0; q < cfr[mi][ni].num_elements; q++)
                    cfr[mi][ni].x[q] = fmaxf(cfr[mi][ni].x[q], 0.f);
            }
            wmma::store_matrix_sync(&C[(size_t)gm * N + n0 + nw + ni * 16], cfr[mi][ni], N,
                                    wmma::mem_row_major);
        }
    }
}

// ---------------- GAT output GEMM, both node types via gridDim.z ----------------
__launch_bounds__(256, 2)
__global__ void gemm_gat_kernel(const float* __restrict__ aggT, const float* __restrict__ aggW,
                                const __nv_bfloat16* __restrict__ Wh,
                                const __nv_bfloat16* __restrict__ Wl,
                                float* __restrict__ Ot, float* __restrict__ Ow,
                                const float* __restrict__ gbias, int NT, int NW)
{
    constexpr int BM = 128, SKA = 32, SKB = 80;
    __shared__ __nv_bfloat16 Ahs[2][BM][SKA];
    __shared__ __nv_bfloat16 Als[2][BM][SKA];
    __shared__ __nv_bfloat16 Bhs[2][16][SKB];
    __shared__ __nv_bfloat16 Bls[2][16][SKB];
    __shared__ float Brep[16][64];

    const int typ = blockIdx.z;
    const int M = typ ? NW : NT;
    const float* A = typ ? aggW : aggT;
    float* C = typ ? Ow : Ot;
    const __nv_bfloat16* WhT = Wh + typ * 32768;
    const __nv_bfloat16* WlT = Wl + typ * 32768;
    const float* bias = gbias + typ * 256;

    const int tid = threadIdx.x;
    const int wid = tid >> 5;
    const int wm = wid & 3, wn = wid >> 2;
    const int h = blockIdx.x;
    const int m0 = blockIdx.y * BM;
    if (m0 >= M) return;
    const int mw = wm * 32, nw = wn * 32;

    float4 ra4[2];
    uint2 rbh2, rbl2;

    auto ldA = [&](int t) {
        int colBase = ((t < 4) ? 0 : 256) + h * 64 + (t & 3) * 16;
#pragma unroll
        for (int i = 0; i < 2; i++) {
            int idx = tid + i * 256;
            int r = idx >> 2, c4 = idx & 3;
            int gm = m0 + r;
            ra4[i] = (gm < M) ? *(const float4*)&A[(size_t)gm * 512 + colBase + c4 * 4]
                              : make_float4(0.f, 0.f, 0.f, 0.f);
        }
    };
    auto stA = [&](int st) {
#pragma unroll
        for (int i = 0; i < 2; i++) {
            int idx = tid + i * 256;
            int r = idx >> 2, c4 = idx & 3;
            float v[4] = {ra4[i].x, ra4[i].y, ra4[i].z, ra4[i].w};
#pragma unroll
            for (int j = 0; j < 4; j++) {
                __nv_bfloat16 hh, ll;
                bf16_split(v[j], hh, ll);
                Ahs[st][r][c4 * 4 + j] = hh;
                Als[st][r][c4 * 4 + j] = ll;
            }
        }
    };
    auto ldB = [&](int t) {
        int blk = ((t < 4) ? 0 : 4) + h;
        int rBase = (t & 3) * 16;
        int r = tid >> 4, c4 = tid & 15;
        rbh2 = *(const uint2*)&WhT[blk * 4096 + (rBase + r) * 64 + c4 * 4];
        rbl2 = *(const uint2*)&WlT[blk * 4096 + (rBase + r) * 64 + c4 * 4];
    };
    auto stB = [&](int st) {
        int r = tid >> 4, c4 = tid & 15;
        *(uint2*)&Bhs[st][r][c4 * 4] = rbh2;
        *(uint2*)&Bls[st][r][c4 * 4] = rbl2;
    };

    ldA(0); ldB(0);
    stA(0); stB(0);
    for (int i = tid; i < 16 * 64; i += 256)
        Brep[i >> 6][i & 63] = bias[h * 64 + (i & 63)];
    __syncthreads();

    wmma::fragment<wmma::accumulator, 16, 16, 16, float> cfr[2][2];
#pragma unroll
    for (int mi = 0; mi < 2; mi++)
#pragma unroll
        for (int ni = 0; ni < 2; ni++)
            wmma::load_matrix_sync(cfr[mi][ni], &Brep[0][nw + ni * 16], 64, wmma::mem_row_major);

    int cur = 0;
    for (int t = 0; t < 8; t++) {
        bool hasNext = (t < 7);
        if (hasNext) { ldA(t + 1); ldB(t + 1); }

        wmma::fragment<wmma::matrix_a, 16, 16, 16, __nv_bfloat16, wmma::row_major> fah[2], fal[2];
#pragma unroll
        for (int mi = 0; mi < 2; mi++) {
            wmma::load_matrix_sync(fah[mi], &Ahs[cur][mw + mi * 16][0], SKA);
            wmma::load_matrix_sync(fal[mi], &Als[cur][mw + mi * 16][0], SKA);
        }
#pragma unroll
        for (int ni = 0; ni < 2; ni++) {
            wmma::fragment<wmma::matrix_b, 16, 16, 16, __nv_bfloat16, wmma::row_major> fbh, fbl;
            wmma::load_matrix_sync(fbh, &Bhs[cur][0][nw + ni * 16], SKB);
            wmma::load_matrix_sync(fbl, &Bls[cur][0][nw + ni * 16], SKB);
#pragma unroll
            for (int mi = 0; mi < 2; mi++) {
                wmma::mma_sync(cfr[mi][ni], fah[mi], fbh, cfr[mi][ni]);
                wmma::mma_sync(cfr[mi][ni], fal[mi], fbh, cfr[mi][ni]);
                wmma::mma_sync(cfr[mi][ni], fah[mi], fbl, cfr[mi][ni]);
            }
        }

        if (hasNext) {
            stA(cur ^ 1); stB(cur ^ 1);
            __syncthreads();
            cur ^= 1;
        }
    }

#pragma unroll
    for (int mi = 0; mi < 2; mi++) {
        int gm = m0 + mw + mi * 16;
#pragma unroll
        for (int ni = 0; ni < 2; ni++) {
#pragma unroll
            for (int q = 0; q < cfr[mi][ni].num_elements; q++)
                cfr[mi][ni].x[q] = fmaxf(cfr[mi][ni].x[q], 0.f);
            wmma::store_matrix_sync(&C[(size_t)gm * 256 + h * 64 + nw + ni * 16], cfr[mi][ni], 256,
                                    wmma::mem_row_major);
        }
    }
}

// ---------------- weight split / pack kernels (tiny) ----------------
__global__ void split_plain2_kernel(const float* __restrict__ s0, int n0,
                                    const float* __restrict__ s1, int n1, int off,
                                    __nv_bfloat16* __restrict__ bh,
                                    __nv_bfloat16* __restrict__ bl)
{
    int i = blockIdx.x * 256 + threadIdx.x;
    if (i < n0) {
        __nv_bfloat16 h, l;
        bf16_split(s0[i], h, l);
        bh[i] = h; bl[i] = l;
    }
    int j = i - n0;
    if (j >= 0 && j < n1) {
        __nv_bfloat16 h, l;
        bf16_split(s1[j], h, l);
        bh[off + j] = h; bl[off + j] = l;
    }
}

__global__ void pack_gatout_kernel(const float* __restrict__ W, const float* __restrict__ gb,
                                   const float* __restrict__ al, const float* __restrict__ ar,
                                   __nv_bfloat16* __restrict__ bh, __nv_bfloat16* __restrict__ bl,
                                   float* __restrict__ gbias,
                                   float* __restrict__ alv, float* __restrict__ arv)
{
    int idx = blockIdx.x * 256 + threadIdx.x;
    if (idx < 65536) {
        int typ = idx >> 15;
        int rem = idx & 32767;
        int b = rem >> 12;              // rel_idx*4 + h
        int k = (rem >> 6) & 63;
        int d = idx & 63;
        int rel = typ + 2 * (b >> 2);
        int h = b & 3;
        float v = 0.5f * W[(size_t)rel * 16384 + k * 256 + h * 64 + d];
        __nv_bfloat16 hh, ll;
        bf16_split(v, hh, ll);
        bh[idx] = hh; bl[idx] = ll;
    }
    if (idx < 512) {
        int typ = idx >> 8, c = idx & 255;
        gbias[idx] = 0.5f * (gb[typ * 256 + c] + gb[(typ + 2) * 256 + c]);
    }
    if (idx >= 65536 && idx < 65536 + 2048) {
        int z = idx - 65536;
        int type = z >> 10;
        int rem = z & 1023;
        int r = rem >> 8;
        int k = (rem >> 2) & 63;
        int h = rem & 3;
        const float* av = type ? ar : al;
        float s = 0.f;
#pragma unroll 16
        for (int d = 0; d < 64; d++)
            s += W[(size_t)r * 16384 + (size_t)k * 256 + h * 64 + d] * av[r * 256 + h * 64 + d];
        (type ? arv : alv)[r * 256 + k * 4 + h] = s;
    }
}

__global__ void pack_sage1_kernel(const float* __restrict__ Ws, const float* __restrict__ Wn,
                                  const float* __restrict__ b,
                                  __nv_bfloat16* __restrict__ bh, __nv_bfloat16* __restrict__ bl,
                                  float* __restrict__ bsum)
{
    int idx = blockIdx.x * 256 + threadIdx.x;
    if (idx < 98304) {
        int typ = idx / 49152;
        int rem = idx - typ * 49152;
        int k = rem / 192;
        int c = rem - k * 192;
        float v;
        if (c < 64) {
            v = typ ? (Ws[16384 + k * 64 + c] + Ws[3 * 16384 + k * 64 + c])
                    : (Ws[k * 64 + c] + Ws[2 * 16384 + k * 64 + c]);
        } else if (c < 128) {
            int rel = typ ? 0 : 1;
            v = Wn[(size_t)rel * 16384 + k * 64 + (c - 64)];
        } else {
            int rel = typ ? 2 : 3;
            v = Wn[(size_t)rel * 16384 + k * 64 + (c - 128)];
        }
        __nv_bfloat16 h, l;
        bf16_split(v, h, l);
        bh[idx] = h; bl[idx] = l;
    }
    if (idx < 384) {
        int typ = idx / 192, c = idx - typ * 192;
        float v = 0.f;
        if (c < 64)
            v = typ ? (b[64 + c] + b[3 * 64 + c]) : (b[c] + b[2 * 64 + c]);
        bsum[idx] = v;
    }
}

// ------------- fused el/er projection -------------
__global__ void vecproj_fused_kernel(const float* __restrict__ Xt, const float* __restrict__ Xw,
                                     const float* __restrict__ alv, const float* __restrict__ arv,
                                     float* __restrict__ el, float* __restrict__ er,
                                     int NT, int NW)
{
    int type = blockIdx.y;
    const float* X = type ? Xw : Xt;
    int n = type ? NW : NT;
    int e0 = type ? 0 : 1;
    int r0 = type ? 1 : 0;

    __shared__ float sv[4][256];
    for (int i = threadIdx.x; i < 1024; i += blockDim.x) {
        int v = i >> 8, c = i & 255;
        const float* src = (v < 2) ? (alv + (e0 + 2 * (v & 1)) * 256)
                                   : (arv + (r0 + 2 * (v & 1)) * 256);
        sv[v][c] = src[c];
    }
    __syncthreads();
    int i = blockIdx.x * blockDim.x + threadIdx.x;
    if (i >= n) return;
    const float* x = X + (size_t)i * 64;
    float a[4][4] = {};
#pragma unroll 8
    for (int k = 0; k < 64; k++) {
        float xv = __ldg(&x[k]);
#pragma unroll
        for (int v = 0; v < 4; v++) {
            float4 s4 = *(const float4*)&sv[v][k * 4];
            a[v][0] += xv * s4.x; a[v][1] += xv * s4.y;
            a[v][2] += xv * s4.z; a[v][3] += xv * s4.w;
        }
    }
    *(float4*)&el[(size_t)(e0)     * MAXN * 4 + (size_t)i * 4] = make_float4(a[0][0], a[0][1], a[0][2], a[0][3]);
    *(float4*)&el[(size_t)(e0 + 2) * MAXN * 4 + (size_t)i * 4] = make_float4(a[1][0], a[1][1], a[1][2], a[1][3]);
    *(float4*)&er[(size_t)(r0)     * MAXN * 4 + (size_t)i * 4] = make_float4(a[2][0], a[2][1], a[2][2], a[2][3]);
    *(float4*)&er[(size_t)(r0 + 2) * MAXN * 4 + (size_t)i * 4] = make_float4(a[3][0], a[3][1], a[3][2], a[3][3]);
}

// ---------------- CSR build ----------------
__global__ void hist_kernel(const int* __restrict__ edges, int* __restrict__ cnt, int E, int n)
{
    for (int idx = blockIdx.x * blockDim.x + threadIdx.x; idx < 4 * E; idx += gridDim.x * blockDim.x) {
        int r = idx / E, i = idx - r * E;
        int dst = edges[(size_t)(2 * r + 1) * E + i];
        atomicAdd(&cnt[r * n + dst], 1);
    }
}

__global__ void scan_kernel(int* __restrict__ cnt, int* __restrict__ rp, int n)
{
    int r = blockIdx.x;
    int t = threadIdx.x;
    int C = (n + 1023) / 1024;
    __shared__ int sums[1024];
    int base = t * C;
    int loc = 0;
    for (int i = 0; i < C; i++) {
        int idx = base + i;
        if (idx < n) loc += cnt[r * n + idx];
    }
    sums[t] = loc;
    __syncthreads();
    for (int off = 1; off < 1024; off <<= 1) {
        int v = (t >= off) ? sums[t - off] : 0;
        __syncthreads();
        sums[t] += v;
        __syncthreads();
    }
    int run = (t == 0) ? 0 : sums[t - 1];
    for (int i = 0; i < C; i++) {
        int idx = base + i;
        if (idx < n) {
            rp[(size_t)r * (n + 1) + idx] = run;
            run += cnt[r * n + idx];
        }
    }
    if (t == 1023) rp[(size_t)r * (n + 1) + n] = sums[1023];
    for (int i = 0; i < C; i++) {
        int idx = base + i;
        if (idx < n) cnt[r * n + idx] = 0;
    }
}

__global__ void scatter_kernel(const int* __restrict__ edges, int* __restrict__ cnt,
                               const int* __restrict__ rp, int* __restrict__ col, int E, int n)
{
    for (int idx = blockIdx.x * blockDim.x + threadIdx.x; idx < 4 * E; idx += gridDim.x * blockDim.x) {
        int r = idx / E, i = idx - r * E;
        int src = edges[(size_t)(2 * r) * E + i];
        int dst = edges[(size_t)(2 * r + 1) * E + i];
        int pos = rp[(size_t)r * (n + 1) + dst] + atomicAdd(&cnt[r * n + dst], 1);
        col[(size_t)r * E + pos] = src;
    }
}

// ---------------- GAT aggregation (pre-projection), two-pass softmax ----------------
__device__ __forceinline__ float lrelu(float x) { return x > 0.f ? x : 0.2f * x; }

__global__ void gat_agg_kernel(float* __restrict__ aggT, float* __restrict__ aggW,
                               const float* __restrict__ Xt, const float* __restrict__ Xw,
                               const float* __restrict__ el, const float* __restrict__ er,
                               const int* __restrict__ rp, const int* __restrict__ col,
                               int NT, int NW, int E)
{
    const size_t EO4 = (size_t)MAXN * 4;
    int yt = blockIdx.y;
    int n = yt ? NW : NT;
    float* agg = yt ? aggW : aggT;
    const float* X = yt ? Xt : Xw;
    int ra = yt, rb = yt + 2;

    int w = (blockIdx.x * blockDim.x + threadIdx.x) >> 5;
    int lane = threadIdx.x & 31;
    if (w >= n) return;

    const int h  = lane >> 3;
    const int dq = (lane & 7) * 2;

    float4 acc[2][2];
#pragma unroll
    for (int q = 0; q < 2; q++) {
        acc[q][0] = make_float4(0.f, 0.f, 0.f, 0.f);
        acc[q][1] = make_float4(0.f, 0.f, 0.f, 0.f);
    }

#pragma unroll
    for (int q = 0; q < 2; q++) {
        int rel = q ? rb : ra;
        const float* elr = el + (size_t)rel * EO4;
        const float* err = er + (size_t)rel * EO4;
        const int* rpr   = rp + (size_t)rel * (MAXN + 1);
        const int* colr  = col + (size_t)rel * E;

        int s0 = rpr[w], s1 = rpr[w + 1];
        if (s1 <= s0) continue;

        float4 e4 = *(const float4*)(err + (size_t)w * 4);
        float er0 = e4.x, er1 = e4.y, er2 = e4.z, er3 = e4.w;

        float m0 = -1e30f, m1 = -1e30f, m2 = -1e30f, m3 = -1e30f;
        for (int e = s0 + lane; e < s1; e += 32) {
            int s = colr[e];
            float4 l4 = *(const float4*)(elr + (size_t)s * 4);
            m0 = fmaxf(m0, lrelu(l4.x + er0));
            m1 = fmaxf(m1, lrelu(l4.y + er1));
            m2 = fmaxf(m2, lrelu(l4.z + er2));
            m3 = fmaxf(m3, lrelu(l4.w + er3));
        }
#pragma unroll
        for (int o = 16; o; o >>= 1) {
            m0 = fmaxf(m0, __shfl_xor_sync(0xffffffffu, m0, o));
            m1 = fmaxf(m1, __shfl_xor_sync(0xffffffffu, m1, o));
            m2 = fmaxf(m2, __shfl_xor_sync(0xffffffffu, m2, o));
            m3 = fmaxf(m3, __shfl_xor_sync(0xffffffffu, m3, o));
        }
        float z0 = 0, z1 = 0, z2 = 0, z3 = 0;
        for (int e = s0 + lane; e < s1; e += 32) {
            int s = colr[e];
            float4 l4 = *(const float4*)(elr + (size_t)s * 4);
            z0 += __expf(lrelu(l4.x + er0) - m0);
            z1 += __expf(lrelu(l4.y + er1) - m1);
            z2 += __expf(lrelu(l4.z + er2) - m2);
            z3 += __expf(lrelu(l4.w + er3) - m3);
        }
#pragma unroll
        for (int o = 16; o; o >>= 1) {
            z0 += __shfl_xor_sync(0xffffffffu, z0, o);
            z1 += __shfl_xor_sync(0xffffffffu, z1, o);
            z2 += __shfl_xor_sync(0xffffffffu, z2, o);
            z3 += __shfl_xor_sync(0xffffffffu, z3, o);
        }

        float mh = (h < 2) ? ((h == 0) ? m0 : m1) : ((h == 2) ? m2 : m3);
        float zh = (h < 2) ? ((h == 0) ? z0 : z1) : ((h == 2) ? z2 : z3);
        float erh = (h < 2) ? ((h == 0) ? er0 : er1) : ((h == 2) ? er2 : er3);
        float ih = 1.f / zh;

        int e = s0;
        for (; e + 1 < s1; e += 2) {
            int sA = colr[e], sB = colr[e + 1];
            float4 lA = *(const float4*)(elr + (size_t)sA * 4);
            float4 lB = *(const float4*)(elr + (size_t)sB * 4);
            const float4* xa = (const float4*)(X + (size_t)sA * 64);
            const float4* xb = (const float4*)(X + (size_t)sB * 64);
            float4 xa0 = xa[dq], xa1 = xa[dq + 1];
            float4 xb0 = xb[dq], xb1 = xb[dq + 1];
            float lvA = (h < 2) ? ((h == 0) ? lA.x : lA.y) : ((h == 2) ? lA.z : lA.w);
            float lvB = (h < 2) ? ((h == 0) ? lB.x : lB.y) : ((h == 2) ? lB.z : lB.w);
            float aA = __expf(lrelu(lvA + erh) - mh) * ih;
            float aB = __expf(lrelu(lvB + erh) - mh) * ih;
            acc[q][0].x = fmaf(aA, xa0.x, acc[q][0].x);
            acc[q][0].y = fmaf(aA, xa0.y, acc[q][0].y);
            acc[q][0].z = fmaf(aA, xa0.z, acc[q][0].z);
            acc[q][0].w = fmaf(aA, xa0.w, acc[q][0].w);
            acc[q][1].x = fmaf(aA, xa1.x, acc[q][1].x);
            acc[q][1].y = fmaf(aA, xa1.y, acc[q][1].y);
            acc[q][1].z = fmaf(aA, xa1.z, acc[q][1].z);
            acc[q][1].w = fmaf(aA, xa1.w, acc[q][1].w);
            acc[q][0].x = fmaf(aB, xb0.x, acc[q][0].x);
            acc[q][0].y = fmaf(aB, xb0.y, acc[q][0].y);
            acc[q][0].z = fmaf(aB, xb0.z, acc[q][0].z);
            acc[q][0].w = fmaf(aB, xb0.w, acc[q][0].w);
            acc[q][1].x = fmaf(aB, xb1.x, acc[q][1].x);
            acc[q][1].y = fmaf(aB, xb1.y, acc[q][1].y);
            acc[q][1].z = fmaf(aB, xb1.z, acc[q][1].z);
            acc[q][1].w = fmaf(aB, xb1.w, acc[q][1].w);
        }
        if (e < s1) {
            int s = colr[e];
            float4 l4 = *(const float4*)(elr + (size_t)s * 4);
            float lv = (h < 2) ? ((h == 0) ? l4.x : l4.y) : ((h == 2) ? l4.z : l4.w);
            float ah = __expf(lrelu(lv + erh) - mh) * ih;
            const float4* xp = (const float4*)(X + (size_t)s * 64);
            float4 x0 = xp[dq], x1 = xp[dq + 1];
            acc[q][0].x = fmaf(ah, x0.x, acc[q][0].x);
            acc[q][0].y = fmaf(ah, x0.y, acc[q][0].y);
            acc[q][0].z = fmaf(ah, x0.z, acc[q][0].z);
            acc[q][0].w = fmaf(ah, x0.w, acc[q][0].w);
            acc[q][1].x = fmaf(ah, x1.x, acc[q][1].x);
            acc[q][1].y = fmaf(ah, x1.y, acc[q][1].y);
            acc[q][1].z = fmaf(ah, x1.z, acc[q][1].z);
            acc[q][1].w = fmaf(ah, x1.w, acc[q][1].w);
        }
    }

    float4* op = (float4*)(agg + (size_t)w * 512);
    int base = h * 16 + (lane & 7) * 2;
    op[base]           = acc[0][0];
    op[base + 1]       = acc[0][1];
    op[64 + base]      = acc[1][0];
    op[64 + base + 1]  = acc[1][1];
}

// ------------- SAGE1 combine, both types via blockIdx.y -------------
__global__ void sage1_combine_kernel(float* __restrict__ t0, float* __restrict__ w0,
    const float* __restrict__ Zt, const float* __restrict__ Zw,
    const int* __restrict__ rp, const int* __restrict__ col,
    int NT, int NW, int E)
{
    int typ = blockIdx.y;
    float* X = typ ? w0 : t0;
    const float* Zself = typ ? Zw : Zt;
    const float* Zsrc  = typ ? Zt : Zw;
    int n = typ ? NW : NT;
    const int* rpa  = rp + (size_t)(typ)     * (MAXN + 1);
    const int* cola = col + (size_t)(typ)     * E;
    const int* rpb  = rp + (size_t)(typ + 2) * (MAXN + 1);
    const int* colb = col + (size_t)(typ + 2) * E;

    int w = (blockIdx.x * blockDim.x + threadIdx.x) >> 5;
    int lane = threadIdx.x & 31;
    if (w >= n) return;
    float mx = 0.f, my = 0.f;
    {
        int s0 = rpa[w], s1 = rpa[w + 1];
        float sx = 0.f, sy = 0.f;
        for (int e = s0; e < s1; e++) {
            int s = cola[e];
            float2 v = *(const float2*)&Zsrc[(size_t)s * 192 + 64 + lane * 2];
            sx += v.x; sy += v.y;
        }
        float inv = 1.f / fmaxf((float)(s1 - s0), 1.f);
        mx += sx * inv; my += sy * inv;
    }
    {
        int s0 = rpb[w], s1 = rpb[w + 1];
        float sx = 0.f, sy = 0.f;
        for (int e = s0; e < s1; e++) {
            int s = colb[e];
            float2 v = *(const float2*)&Zsrc[(size_t)s * 192 + 128 + lane * 2];
            sx += v.x; sy += v.y;
        }
        float inv = 1.f / fmaxf((float)(s1 - s0), 1.f);
        mx += sx * inv; my += sy * inv;
    }
    float2 sv = *(const float2*)&Zself[(size_t)w * 192 + lane * 2];
    float2 o;
    o.x = fmaxf(sv.x + mx, 0.f);
    o.y = fmaxf(sv.y + my, 0.f);
    *(float2*)&X[(size_t)w * 64 + lane * 2] = o;
}

// ------------- SAGE2 projections, both types via blockIdx.y -------------
__global__ void proj6_kernel(const float* __restrict__ t1, const float* __restrict__ w1,
    const float* __restrict__ Ws, const float* __restrict__ Wn,
    float* __restrict__ el, float* __restrict__ er, int NT, int NW)
{
    const size_t Y2 = (size_t)MAXN * 2;
    int typ = blockIdx.y;
    const float* X = typ ? w1 : t1;
    int n = typ ? NW : NT;
    const float* WsA = Ws + (typ ? 1 : 0) * 512;
    const float* WsB = Ws + (typ ? 3 : 2) * 512;
    const float* WnA = Wn + (typ ? 0 : 1) * 512;
    const float* WnB = Wn + (typ ? 2 : 3) * 512;
    float* selfO = er + (size_t)typ * Y2;
    float* yA = el + (size_t)(typ ? 0 : 1) * Y2;
    float* yB = el + (size_t)(typ ? 2 : 3) * Y2;

    __shared__ float sw[3][512];
    for (int i = threadIdx.x; i < 512; i += blockDim.x) {
        sw[0][i] = WsA[i] + WsB[i];
        sw[1][i] = WnA[i];
        sw[2][i] = WnB[i];
    }
    __syncthreads();
    int w = (blockIdx.x * blockDim.x + threadIdx.x) >> 5;
    int lane = threadIdx.x & 31;
    if (w >= n) return;
    float a[6] = {0.f, 0.f, 0.f, 0.f, 0.f, 0.f};
    for (int k = lane; k < 256; k += 32) {
        float x = X[(size_t)w * 256 + k];
        a[0] += x * sw[0][2 * k]; a[1] += x * sw[0][2 * k + 1];
        a[2] += x * sw[1][2 * k]; a[3] += x * sw[1][2 * k + 1];
        a[4] += x * sw[2][2 * k]; a[5] += x * sw[2][2 * k + 1];
    }
#pragma unroll
    for (int o = 16; o; o >>= 1)
#pragma unroll
        for (int j = 0; j < 6; j++)
            a[j] += __shfl_xor_sync(0xffffffffu, a[j], o);
    if (lane == 0) {
        *(float2*)&selfO[(size_t)w * 2] = make_float2(a[0], a[1]);
        *(float2*)&yA[(size_t)w * 2]    = make_float2(a[2], a[3]);
        *(float2*)&yB[(size_t)w * 2]    = make_float2(a[4], a[5]);
    }
}

// ------------- SAGE2 combine, both types via blockIdx.y -------------
__global__ void sage2_combine_kernel(float* __restrict__ fout,
    const float* __restrict__ el, const float* __restrict__ er,
    const int* __restrict__ rp, const int* __restrict__ col,
    const float* __restrict__ b, int NT, int NW, int E)
{
    const size_t Y2 = (size_t)MAXN * 2;
    int typ = blockIdx.y;
    int n = typ ? NW : NT;
    float* out = fout + (typ ? (size_t)NT * 2 : 0);
    const float* selfO = er + (size_t)typ * Y2;
    const float* yA = el + (size_t)(typ)     * Y2;
    const float* yB = el + (size_t)(typ + 2) * Y2;
    const int* rpa  = rp + (size_t)(typ)     * (MAXN + 1);
    const int* cola = col + (size_t)(typ)     * E;
    const int* rpb  = rp + (size_t)(typ + 2) * (MAXN + 1);
    const int* colb = col + (size_t)(typ + 2) * E;
    const float* bA = b + typ * 2;
    const float* bB = b + (typ + 2) * 2;

    int w = blockIdx.x * blockDim.x + threadIdx.x;
    if (w >= n) return;
    float2 r = *(const float2*)&selfO[(size_t)w * 2];
    r.x += bA[0] + bB[0];
    r.y += bA[1] + bB[1];
    {
        int s0 = rpa[w], s1 = rpa[w + 1];
        float sx = 0.f, sy = 0.f;
        for (int e = s0; e < s1; e++) {
            float2 v = *(const float2*)&yA[(size_t)cola[e] * 2];
            sx += v.x; sy += v.y;
        }
        float inv = 1.f / fmaxf((float)(s1 - s0), 1.f);
        r.x += sx * inv; r.y += sy * inv;
    }
    {
        int s0 = rpb[w], s1 = rpb[w + 1];
        float sx = 0.f, sy = 0.f;
        for (int e = s0; e < s1; e++) {
            float2 v = *(const float2*)&yB[(size_t)colb[e] * 2];
            sx += v.x; sy += v.y;
        }
        float inv = 1.f / fmaxf((float)(s1 - s0), 1.f);
        r.x += sx * inv; r.y += sy * inv;
    }
    *(float2*)&out[(size_t)w * 2] = r;
}

// ---------------- host helpers ----------------
static void gemm_bs(const float* A, const __nv_bfloat16* Bh, const __nv_bfloat16* Bl, float* C,
                    const float* bias, int M, int N, int K, int relu, cudaStream_t st = 0)
{
    dim3 g(N / 64, (M + 127) / 128);
    if ((K & 15) == 0) gemm_bs_kernel<true><<<g, 256, 0, st>>>(A, Bh, Bl, C, bias, M, N, K, relu);
    else               gemm_bs_kernel<false><<<g, 256, 0, st>>>(A, Bh, Bl, C, bias, M, N, K, relu);
}

extern "C" void kernel_launch(void* const* d_in, const int* in_sizes, int n_in,
                              void* d_out, int out_size)
{
    const float* tx_feat  = (const float*)d_in[0];
    const float* w_feat   = (const float*)d_in[1];
    const int*   edges    = (const int*)d_in[2];
    const float* tx_W     = (const float*)d_in[3];
    const float* tx_b     = (const float*)d_in[4];
    const float* w_W      = (const float*)d_in[5];
    const float* w_b      = (const float*)d_in[6];
    const float* gat1_W   = (const float*)d_in[7];
    const float* gat1_al  = (const float*)d_in[8];
    const float* gat1_ar  = (const float*)d_in[9];
    const float* gat1_b   = (const float*)d_in[10];
    const float* sage1_Ws = (const float*)d_in[11];
    const float* sage1_Wn = (const float*)d_in[12];
    const float* sage1_b  = (const float*)d_in[13];
    const float* gat2_W   = (const float*)d_in[14];
    const float* gat2_al  = (const float*)d_in[15];
    const float* gat2_ar  = (const float*)d_in[16];
    const float* gat2_b   = (const float*)d_in[17];
    const float* sage2_Ws = (const float*)d_in[18];
    const float* sage2_Wn = (const float*)d_in[19];
    const float* sage2_b  = (const float*)d_in[20];

    int NT = in_sizes[0] / 166;
    int NW = in_sizes[1] / 56;
    int E  = in_sizes[2] / 8;
    if (NT > MAXN) NT = MAXN;
    if (NW > MAXN) NW = MAXN;
    if (E > MAXE) E = MAXE;

    float *t0, *w0, *t1, *w1, *hs, *el, *er, *alv, *arv, *bsum, *gbias;
    __nv_bfloat16 *bh, *bl;
    int *cnt, *rp, *col;
    cudaGetSymbolAddress((void**)&t0, d_t0);
    cudaGetSymbolAddress((void**)&w0, d_w0);
    cudaGetSymbolAddress((void**)&t1, d_t1);
    cudaGetSymbolAddress((void**)&w1, d_w1);
    cudaGetSymbolAddress((void**)&hs, d_hs);
    cudaGetSymbolAddress((void**)&el, d_el);
    cudaGetSymbolAddress((void**)&er, d_er);
    cudaGetSymbolAddress((void**)&alv, d_alv);
    cudaGetSymbolAddress((void**)&arv, d_arv);
    cudaGetSymbolAddress((void**)&bh, d_bh16);
    cudaGetSymbolAddress((void**)&bl, d_bl16);
    cudaGetSymbolAddress((void**)&bsum, d_bsum);
    cudaGetSymbolAddress((void**)&gbias, d_gbias);
    cudaGetSymbolAddress((void**)&cnt, d_cnt);
    cudaGetSymbolAddress((void**)&rp, d_rpv);
    cudaGetSymbolAddress((void**)&col, d_colv);

    float* fout = (float*)d_out;
    float* aggT = hs;
    float* aggW = hs + (size_t)MAXN * 512;
    float* Zt = hs;
    float* Zw = hs + (size_t)MAXN * 512;
    int nmax = NT > NW ? NT : NW;

    // ---- one-time stream/event setup (first call is not graph-captured) ----
    static cudaStream_t s2 = nullptr, s3 = nullptr;
    static cudaEvent_t evFork = nullptr, evJoin = nullptr, evSplit = nullptr, evS3 = nullptr;
    if (!s2) {
        cudaStreamCreateWithFlags(&s2, cudaStreamNonBlocking);
        cudaStreamCreateWithFlags(&s3, cudaStreamNonBlocking);
        cudaEventCreateWithFlags(&evFork, cudaEventDisableTiming);
        cudaEventCreateWithFlags(&evJoin, cudaEventDisableTiming);
        cudaEventCreateWithFlags(&evSplit, cudaEventDisableTiming);
        cudaEventCreateWithFlags(&evS3, cudaEventDisableTiming);
    }

    // ---- fork ----
    cudaEventRecord(evFork, 0);
    cudaStreamWaitEvent(s2, evFork, 0);
    cudaStreamWaitEvent(s3, evFork, 0);

    // s2: CSR build (edges only)
    cudaMemsetAsync(cnt, 0, 4 * (size_t)MAXN * sizeof(int), s2);
    hist_kernel<<<(4 * E + 255) / 256, 256, 0, s2>>>(edges, cnt, E, NT);
    scan_kernel<<<4, 1024, 0, s2>>>(cnt, rp, NT);
    scatter_kernel<<<(4 * E + 255) / 256, 256, 0, s2>>>(edges, cnt, rp, col, E, NT);
    cudaEventRecord(evJoin, s2);

    // s3: all weight packs (weights only), then w input projection
    pack_gatout_kernel<<<265, 256, 0, s3>>>(gat1_W, gat1_b, gat1_al, gat1_ar,
                                            bh + G1OFF, bl + G1OFF, gbias, alv, arv);
    pack_gatout_kernel<<<265, 256, 0, s3>>>(gat2_W, gat2_b, gat2_al, gat2_ar,
                                            bh + G2OFF, bl + G2OFF, gbias + 512,
                                            alv + 1024, arv + 1024);
    pack_sage1_kernel<<<384, 256, 0, s3>>>(sage1_Ws, sage1_Wn, sage1_b,
                                           bh + S1OFF, bl + S1OFF, bsum);

    // main: input weight split, then t projection; w projection on s3
    split_plain2_kernel<<<(166 * 64 + 56 * 64 + 255) / 256, 256>>>(
        tx_W, 166 * 64, w_W, 56 * 64, 166 * 64, bh + INOFF, bl + INOFF);
    cudaEventRecord(evSplit, 0);
    cudaStreamWaitEvent(s3, evSplit, 0);
    gemm_bs(w_feat, bh + INOFF + 166 * 64, bl + INOFF + 166 * 64, w0, w_b, NW, 64, 56, 1, s3);
    cudaEventRecord(evS3, s3);

    gemm_bs(tx_feat, bh + INOFF, bl + INOFF, t0, tx_b, NT, 64, 166, 1);

    // join s3 (w0 + all packs ready), then GAT1 el/er projection
    cudaStreamWaitEvent(0, evS3, 0);
    {
        dim3 gv((nmax + 255) / 256, 2);
        vecproj_fused_kernel<<<gv, 256>>>(t0, w0, alv, arv, el, er, NT, NW);
    }

    // join s2 (CSR ready), then edge-dependent work
    cudaStreamWaitEvent(0, evJoin, 0);
    {
        dim3 ga((nmax + 7) / 8, 2);
        gat_agg_kernel<<<ga, 256>>>(aggT, aggW, t0, w0, el, er, rp, col, NT, NW, E);
        gemm_gat_kernel<<<dim3(4, (nmax + 127) / 128, 2), 256>>>(aggT, aggW, bh + G1OFF, bl + G1OFF,
                                                                 t1, w1, gbias, NT, NW);
    }

    // ---- S2: hetero SAGE1 (256 -> 64): one fused N=192 GEMM per type ----
    {
        gemm_bs(t1, bh + S1OFF,         bl + S1OFF,         Zt, bsum,       NT, 192, 256, 0);
        gemm_bs(w1, bh + S1OFF + 49152, bl + S1OFF + 49152, Zw, bsum + 192, NW, 192, 256, 0);
        dim3 gc((nmax + 7) / 8, 2);
        sage1_combine_kernel<<<gc, 256>>>(t0, w0, Zt, Zw, rp, col, NT, NW, E);
    }

    // ---- S3: hetero GAT2 (64 -> 256): aggregate-then-project (weights pre-packed) ----
    {
        dim3 gv((nmax + 255) / 256, 2);
        vecproj_fused_kernel<<<gv, 256>>>(t0, w0, alv + 1024, arv + 1024, el, er, NT, NW);
        dim3 ga((nmax + 7) / 8, 2);
        gat_agg_kernel<<<ga, 256>>>(aggT, aggW, t0, w0, el, er, rp, col, NT, NW, E);
        gemm_gat_kernel<<<dim3(4, (nmax + 127) / 128, 2), 256>>>(aggT, aggW, bh + G2OFF, bl + G2OFF,
                                                                 t1, w1, gbias + 512, NT, NW);
    }

    // ---- S4: hetero SAGE2 (256 -> 2): project-then-aggregate ----
    {
        dim3 gp((nmax + 7) / 8, 2);
        proj6_kernel<<<gp, 256>>>(t1, w1, sage2_Ws, sage2_Wn, el, er, NT, NW);
        dim3 gs((nmax + 255) / 256, 2);
        sage2_combine_kernel<<<gs, 256>>>(fout, el, er, rp, col, sage2_b, NT, NW, E);
    }
}

// round 17
// speedup vs baseline: 1.0182x; 1.0182x over previous
#include <cuda_runtime.h>
#include <cuda_bf16.h>
#include <mma.h>
#include <cstdint>
#include <cstddef>

using namespace nvcuda;

#define MAXN 50000
#define MAXE 400000
#define PAD_ROWS 128
// weight-buffer regions inside d_bh16/d_bl16
#define INOFF 0            // input W splits (166*64 + 56*64 = 14208)
#define G1OFF 16384        // gat1 pack (65536)
#define G2OFF 81920        // gat2 pack (65536)
#define S1OFF 147456       // sage1 pack (98304) -> end 245760

// ---------------- persistent device scratch (padded for unguarded GEMM tail stores) ------------
__device__ float d_t0[((size_t)MAXN + PAD_ROWS) * 256];
__device__ float d_w0[((size_t)MAXN + PAD_ROWS) * 256];
__device__ float d_t1[((size_t)MAXN + PAD_ROWS) * 256];
__device__ float d_w1[((size_t)MAXN + PAD_ROWS) * 256];
__device__ float d_hs[(size_t)MAXN * 1024 + PAD_ROWS * 512];  // agg buffers / fused SAGE1 Z
__device__ float d_el[4 * (size_t)MAXN * 4];
__device__ float d_er[4 * (size_t)MAXN * 4];
__device__ float d_alv[2048];          // per-layer: +0 / +1024
__device__ float d_arv[2048];
__device__ unsigned d_elmax[2][16];    // per-layer (rel*4+head) el max, order-preserving encoding
__device__ __nv_bfloat16 d_bh16[245760];
__device__ __nv_bfloat16 d_bl16[245760];
__device__ float d_bsum[384];
__device__ float d_gbias[1024];        // per-layer: +0 / +512
__device__ int   d_cnt[4 * MAXN];
__device__ int   d_rpv[4 * (MAXN + 1)];
__device__ int   d_colv[4 * MAXE];

__device__ __forceinline__ void bf16_split(float v, __nv_bfloat16& h, __nv_bfloat16& l)
{
    h = __float2bfloat16(v);
    l = __float2bfloat16(v - __bfloat162float(h));
}

// order-preserving float<->unsigned for atomicMax
__device__ __forceinline__ unsigned fenc(float f)
{
    int i = __float_as_int(f);
    return (i >= 0) ? ((unsigned)i | 0x80000000u) : ~((unsigned)i);
}
__device__ __forceinline__ float fdec(unsigned k)
{
    int i = (k & 0x80000000u) ? (int)(k & 0x7FFFFFFFu) : ~(int)k;
    return __int_as_float(i);
}

// ---------------- BF16 split tensor-core GEMM with pre-split B ----------------
template<bool VEC>
__launch_bounds__(256, 2)
__global__ void gemm_bs_kernel(const float* __restrict__ A,
                               const __nv_bfloat16* __restrict__ Bh,
                               const __nv_bfloat16* __restrict__ Bl,
                               float* __restrict__ C, const float* __restrict__ bias,
                               int M, int N, int K, int relu)
{
    constexpr int BM = 128, BN = 64, SKA = 32, SKB = 80;
    __shared__ __nv_bfloat16 Ahs[2][BM][SKA];
    __shared__ __nv_bfloat16 Als[2][BM][SKA];
    __shared__ __nv_bfloat16 Bhs[2][16][SKB];
    __shared__ __nv_bfloat16 Bls[2][16][SKB];
    __shared__ float Brep[16][BN];

    const int tid = threadIdx.x;
    const int wid = tid >> 5;
    const int wm = wid & 3, wn = wid >> 2;
    const int m0 = blockIdx.y * BM, n0 = blockIdx.x * BN;
    const int mw = wm * 32;
    const int nw = wn * 32;

    float4 ra4[2];  float ras[8];
    uint2 rbh2;     __nv_bfloat16 rbhs[4];
    uint2 rbl2;     __nv_bfloat16 rbls[4];

    auto ldA = [&](int t) {
        int k0 = t * 16;
        if (VEC) {
#pragma unroll
            for (int i = 0; i < 2; i++) {
                int idx = tid + i * 256;
                int r = idx >> 2, c4 = idx & 3;
                int gm = m0 + r;
                ra4[i] = (gm < M) ? *(const float4*)&A[(size_t)gm * K + k0 + c4 * 4]
                                  : make_float4(0.f, 0.f, 0.f, 0.f);
            }
        } else {
#pragma unroll
            for (int i = 0; i < 8; i++) {
                int idx = tid + i * 256;
                int r = idx >> 4, c = idx & 15;
                int gm = m0 + r;
                ras[i] = (gm < M && k0 + c < K) ? A[(size_t)gm * K + k0 + c] : 0.f;
            }
        }
    };
    auto stA = [&](int st) {
        if (VEC) {
#pragma unroll
            for (int i = 0; i < 2; i++) {
                int idx = tid + i * 256;
                int r = idx >> 2, c4 = idx & 3;
                float v[4] = {ra4[i].x, ra4[i].y, ra4[i].z, ra4[i].w};
#pragma unroll
                for (int j = 0; j < 4; j++) {
                    __nv_bfloat16 h, l;
                    bf16_split(v[j], h, l);
                    Ahs[st][r][c4 * 4 + j] = h;
                    Als[st][r][c4 * 4 + j] = l;
                }
            }
        } else {
#pragma unroll
            for (int i = 0; i < 8; i++) {
                int idx = tid + i * 256;
                int r = idx >> 4, c = idx & 15;
                __nv_bfloat16 h, l;
                bf16_split(ras[i], h, l);
                Ahs[st][r][c] = h;
                Als[st][r][c] = l;
            }
        }
    };
    auto ldB = [&](int t) {
        int k0 = t * 16;
        if (VEC) {
            int r = tid >> 4, c4 = tid & 15;
            rbh2 = *(const uint2*)&Bh[(size_t)(k0 + r) * N + n0 + c4 * 4];
            rbl2 = *(const uint2*)&Bl[(size_t)(k0 + r) * N + n0 + c4 * 4];
        } else {
#pragma unroll
            for (int i = 0; i < 4; i++) {
                int idx = tid + i * 256;
                int r = idx >> 6, c = idx & 63;
                bool ok = (k0 + r) < K;
                rbhs[i] = ok ? Bh[(size_t)(k0 + r) * N + n0 + c] : __float2bfloat16(0.f);
                rbls[i] = ok ? Bl[(size_t)(k0 + r) * N + n0 + c] : __float2bfloat16(0.f);
            }
        }
    };
    auto stB = [&](int st) {
        if (VEC) {
            int r = tid >> 4, c4 = tid & 15;
            *(uint2*)&Bhs[st][r][c4 * 4] = rbh2;
            *(uint2*)&Bls[st][r][c4 * 4] = rbl2;
        } else {
#pragma unroll
            for (int i = 0; i < 4; i++) {
                int idx = tid + i * 256;
                int r = idx >> 6, c = idx & 63;
                Bhs[st][r][c] = rbhs[i];
                Bls[st][r][c] = rbls[i];
            }
        }
    };

    ldA(0); ldB(0);
    stA(0); stB(0);
    if (bias) {
        for (int i = tid; i < 16 * BN; i += 256)
            Brep[i >> 6][i & 63] = bias[n0 + (i & 63)];
    }
    __syncthreads();

    wmma::fragment<wmma::accumulator, 16, 16, 16, float> cfr[2][2];
#pragma unroll
    for (int mi = 0; mi < 2; mi++)
#pragma unroll
        for (int ni = 0; ni < 2; ni++) {
            if (bias)
                wmma::load_matrix_sync(cfr[mi][ni], &Brep[0][nw + ni * 16], BN, wmma::mem_row_major);
            else
                wmma::fill_fragment(cfr[mi][ni], 0.f);
        }

    const int numK = (K + 15) >> 4;
    int cur = 0;
    for (int t = 0; t < numK; t++) {
        bool hasNext = (t + 1 < numK);
        if (hasNext) { ldA(t + 1); ldB(t + 1); }

        wmma::fragment<wmma::matrix_a, 16, 16, 16, __nv_bfloat16, wmma::row_major> fah[2], fal[2];
#pragma unroll
        for (int mi = 0; mi < 2; mi++) {
            wmma::load_matrix_sync(fah[mi], &Ahs[cur][mw + mi * 16][0], SKA);
            wmma::load_matrix_sync(fal[mi], &Als[cur][mw + mi * 16][0], SKA);
        }
#pragma unroll
        for (int ni = 0; ni < 2; ni++) {
            wmma::fragment<wmma::matrix_b, 16, 16, 16, __nv_bfloat16, wmma::row_major> fbh, fbl;
            wmma::load_matrix_sync(fbh, &Bhs[cur][0][nw + ni * 16], SKB);
            wmma::load_matrix_sync(fbl, &Bls[cur][0][nw + ni * 16], SKB);
#pragma unroll
            for (int mi = 0; mi < 2; mi++) {
                wmma::mma_sync(cfr[mi][ni], fah[mi], fbh, cfr[mi][ni]);
                wmma::mma_sync(cfr[mi][ni], fal[mi], fbh, cfr[mi][ni]);
                wmma::mma_sync(cfr[mi][ni], fah[mi], fbl, cfr[mi][ni]);
            }
        }

        if (hasNext) {
            stA(cur ^ 1); stB(cur ^ 1);
            __syncthreads();
            cur ^= 1;
        }
    }

#pragma unroll
    for (int mi = 0; mi < 2; mi++) {
        int gm = m0 + mw + mi * 16;
#pragma unroll
        for (int ni = 0; ni < 2; ni++) {
            if (relu) {
#pragma unroll
                for (int q = 0; q < cfr[mi][ni].num_elements; q++)
                    cfr[mi][ni].x[q] = fmaxf(cfr[mi][ni].x[q], 0.f);
            }
            wmma::store_matrix_sync(&C[(size_t)gm * N + n0 + nw + ni * 16], cfr[mi][ni], N,
                                    wmma::mem_row_major);
        }
    }
}

// ---------------- GAT output GEMM, both node types via gridDim.z ----------------
__launch_bounds__(256, 2)
__global__ void gemm_gat_kernel(const float* __restrict__ aggT, const float* __restrict__ aggW,
                                const __nv_bfloat16* __restrict__ Wh,
                                const __nv_bfloat16* __restrict__ Wl,
                                float* __restrict__ Ot, float* __restrict__ Ow,
                                const float* __restrict__ gbias, int NT, int NW)
{
    constexpr int BM = 128, SKA = 32, SKB = 80;
    __shared__ __nv_bfloat16 Ahs[2][BM][SKA];
    __shared__ __nv_bfloat16 Als[2][BM][SKA];
    __shared__ __nv_bfloat16 Bhs[2][16][SKB];
    __shared__ __nv_bfloat16 Bls[2][16][SKB];
    __shared__ float Brep[16][64];

    const int typ = blockIdx.z;
    const int M = typ ? NW : NT;
    const float* A = typ ? aggW : aggT;
    float* C = typ ? Ow : Ot;
    const __nv_bfloat16* WhT = Wh + typ * 32768;
    const __nv_bfloat16* WlT = Wl + typ * 32768;
    const float* bias = gbias + typ * 256;

    const int tid = threadIdx.x;
    const int wid = tid >> 5;
    const int wm = wid & 3, wn = wid >> 2;
    const int h = blockIdx.x;
    const int m0 = blockIdx.y * BM;
    if (m0 >= M) return;
    const int mw = wm * 32, nw = wn * 32;

    float4 ra4[2];
    uint2 rbh2, rbl2;

    auto ldA = [&](int t) {
        int colBase = ((t < 4) ? 0 : 256) + h * 64 + (t & 3) * 16;
#pragma unroll
        for (int i = 0; i < 2; i++) {
            int idx = tid + i * 256;
            int r = idx >> 2, c4 = idx & 3;
            int gm = m0 + r;
            ra4[i] = (gm < M) ? *(const float4*)&A[(size_t)gm * 512 + colBase + c4 * 4]
                              : make_float4(0.f, 0.f, 0.f, 0.f);
        }
    };
    auto stA = [&](int st) {
#pragma unroll
        for (int i = 0; i < 2; i++) {
            int idx = tid + i * 256;
            int r = idx >> 2, c4 = idx & 3;
            float v[4] = {ra4[i].x, ra4[i].y, ra4[i].z, ra4[i].w};
#pragma unroll
            for (int j = 0; j < 4; j++) {
                __nv_bfloat16 hh, ll;
                bf16_split(v[j], hh, ll);
                Ahs[st][r][c4 * 4 + j] = hh;
                Als[st][r][c4 * 4 + j] = ll;
            }
        }
    };
    auto ldB = [&](int t) {
        int blk = ((t < 4) ? 0 : 4) + h;
        int rBase = (t & 3) * 16;
        int r = tid >> 4, c4 = tid & 15;
        rbh2 = *(const uint2*)&WhT[blk * 4096 + (rBase + r) * 64 + c4 * 4];
        rbl2 = *(const uint2*)&WlT[blk * 4096 + (rBase + r) * 64 + c4 * 4];
    };
    auto stB = [&](int st) {
        int r = tid >> 4, c4 = tid & 15;
        *(uint2*)&Bhs[st][r][c4 * 4] = rbh2;
        *(uint2*)&Bls[st][r][c4 * 4] = rbl2;
    };

    ldA(0); ldB(0);
    stA(0); stB(0);
    for (int i = tid; i < 16 * 64; i += 256)
        Brep[i >> 6][i & 63] = bias[h * 64 + (i & 63)];
    __syncthreads();

    wmma::fragment<wmma::accumulator, 16, 16, 16, float> cfr[2][2];
#pragma unroll
    for (int mi = 0; mi < 2; mi++)
#pragma unroll
        for (int ni = 0; ni < 2; ni++)
            wmma::load_matrix_sync(cfr[mi][ni], &Brep[0][nw + ni * 16], 64, wmma::mem_row_major);

    int cur = 0;
    for (int t = 0; t < 8; t++) {
        bool hasNext = (t < 7);
        if (hasNext) { ldA(t + 1); ldB(t + 1); }

        wmma::fragment<wmma::matrix_a, 16, 16, 16, __nv_bfloat16, wmma::row_major> fah[2], fal[2];
#pragma unroll
        for (int mi = 0; mi < 2; mi++) {
            wmma::load_matrix_sync(fah[mi], &Ahs[cur][mw + mi * 16][0], SKA);
            wmma::load_matrix_sync(fal[mi], &Als[cur][mw + mi * 16][0], SKA);
        }
#pragma unroll
        for (int ni = 0; ni < 2; ni++) {
            wmma::fragment<wmma::matrix_b, 16, 16, 16, __nv_bfloat16, wmma::row_major> fbh, fbl;
            wmma::load_matrix_sync(fbh, &Bhs[cur][0][nw + ni * 16], SKB);
            wmma::load_matrix_sync(fbl, &Bls[cur][0][nw + ni * 16], SKB);
#pragma unroll
            for (int mi = 0; mi < 2; mi++) {
                wmma::mma_sync(cfr[mi][ni], fah[mi], fbh, cfr[mi][ni]);
                wmma::mma_sync(cfr[mi][ni], fal[mi], fbh, cfr[mi][ni]);
                wmma::mma_sync(cfr[mi][ni], fah[mi], fbl, cfr[mi][ni]);
            }
        }

        if (hasNext) {
            stA(cur ^ 1); stB(cur ^ 1);
            __syncthreads();
            cur ^= 1;
        }
    }

#pragma unroll
    for (int mi = 0; mi < 2; mi++) {
        int gm = m0 + mw + mi * 16;
#pragma unroll
        for (int ni = 0; ni < 2; ni++) {
#pragma unroll
            for (int q = 0; q < cfr[mi][ni].num_elements; q++)
                cfr[mi][ni].x[q] = fmaxf(cfr[mi][ni].x[q], 0.f);
            wmma::store_matrix_sync(&C[(size_t)gm * 256 + h * 64 + nw + ni * 16], cfr[mi][ni], 256,
                                    wmma::mem_row_major);
        }
    }
}

// ---------------- weight split / pack kernels (tiny) ----------------
__global__ void split_plain2_kernel(const float* __restrict__ s0, int n0,
                                    const float* __restrict__ s1, int n1, int off,
                                    __nv_bfloat16* __restrict__ bh,
                                    __nv_bfloat16* __restrict__ bl)
{
    int i = blockIdx.x * 256 + threadIdx.x;
    if (i < n0) {
        __nv_bfloat16 h, l;
        bf16_split(s0[i], h, l);
        bh[i] = h; bl[i] = l;
    }
    int j = i - n0;
    if (j >= 0 && j < n1) {
        __nv_bfloat16 h, l;
        bf16_split(s1[j], h, l);
        bh[off + j] = h; bl[off + j] = l;
    }
}

__global__ void pack_gatout_kernel(const float* __restrict__ W, const float* __restrict__ gb,
                                   const float* __restrict__ al, const float* __restrict__ ar,
                                   __nv_bfloat16* __restrict__ bh, __nv_bfloat16* __restrict__ bl,
                                   float* __restrict__ gbias,
                                   float* __restrict__ alv, float* __restrict__ arv,
                                   unsigned* __restrict__ elmax)
{
    int idx = blockIdx.x * 256 + threadIdx.x;
    if (idx < 65536) {
        int typ = idx >> 15;
        int rem = idx & 32767;
        int b = rem >> 12;              // rel_idx*4 + h
        int k = (rem >> 6) & 63;
        int d = idx & 63;
        int rel = typ + 2 * (b >> 2);
        int h = b & 3;
        float v = 0.5f * W[(size_t)rel * 16384 + k * 256 + h * 64 + d];
        __nv_bfloat16 hh, ll;
        bf16_split(v, hh, ll);
        bh[idx] = hh; bl[idx] = ll;
    }
    if (idx < 512) {
        int typ = idx >> 8, c = idx & 255;
        gbias[idx] = 0.5f * (gb[typ * 256 + c] + gb[(typ + 2) * 256 + c]);
    }
    if (idx < 16) elmax[idx] = 0u;      // identity for encoded atomicMax
    if (idx >= 65536 && idx < 65536 + 2048) {
        int z = idx - 65536;
        int type = z >> 10;
        int rem = z & 1023;
        int r = rem >> 8;
        int k = (rem >> 2) & 63;
        int h = rem & 3;
        const float* av = type ? ar : al;
        float s = 0.f;
#pragma unroll 16
        for (int d = 0; d < 64; d++)
            s += W[(size_t)r * 16384 + (size_t)k * 256 + h * 64 + d] * av[r * 256 + h * 64 + d];
        (type ? arv : alv)[r * 256 + k * 4 + h] = s;
    }
}

__global__ void pack_sage1_kernel(const float* __restrict__ Ws, const float* __restrict__ Wn,
                                  const float* __restrict__ b,
                                  __nv_bfloat16* __restrict__ bh, __nv_bfloat16* __restrict__ bl,
                                  float* __restrict__ bsum)
{
    int idx = blockIdx.x * 256 + threadIdx.x;
    if (idx < 98304) {
        int typ = idx / 49152;
        int rem = idx - typ * 49152;
        int k = rem / 192;
        int c = rem - k * 192;
        float v;
        if (c < 64) {
            v = typ ? (Ws[16384 + k * 64 + c] + Ws[3 * 16384 + k * 64 + c])
                    : (Ws[k * 64 + c] + Ws[2 * 16384 + k * 64 + c]);
        } else if (c < 128) {
            int rel = typ ? 0 : 1;
            v = Wn[(size_t)rel * 16384 + k * 64 + (c - 64)];
        } else {
            int rel = typ ? 2 : 3;
            v = Wn[(size_t)rel * 16384 + k * 64 + (c - 128)];
        }
        __nv_bfloat16 h, l;
        bf16_split(v, h, l);
        bh[idx] = h; bl[idx] = l;
    }
    if (idx < 384) {
        int typ = idx / 192, c = idx - typ * 192;
        float v = 0.f;
        if (c < 64)
            v = typ ? (b[64 + c] + b[3 * 64 + c]) : (b[c] + b[2 * 64 + c]);
        bsum[idx] = v;
    }
}

// ------------- fused el/er projection + per-(rel,head) el max -------------
__global__ void vecproj_fused_kernel(const float* __restrict__ Xt, const float* __restrict__ Xw,
                                     const float* __restrict__ alv, const float* __restrict__ arv,
                                     float* __restrict__ el, float* __restrict__ er,
                                     unsigned* __restrict__ elmax, int NT, int NW)
{
    int type = blockIdx.y;
    const float* X = type ? Xw : Xt;
    int n = type ? NW : NT;
    int e0 = type ? 0 : 1;
    int r0 = type ? 1 : 0;

    __shared__ float sv[4][256];
    for (int i = threadIdx.x; i < 1024; i += blockDim.x) {
        int v = i >> 8, c = i & 255;
        const float* src = (v < 2) ? (alv + (e0 + 2 * (v & 1)) * 256)
                                   : (arv + (r0 + 2 * (v & 1)) * 256);
        sv[v][c] = src[c];
    }
    __syncthreads();
    int i = blockIdx.x * blockDim.x + threadIdx.x;
    bool valid = (i < n);
    float a[4][4];
#pragma unroll
    for (int v = 0; v < 4; v++)
#pragma unroll
        for (int j = 0; j < 4; j++) a[v][j] = valid ? 0.f : -3e38f;

    if (valid) {
        const float* x = X + (size_t)i * 64;
#pragma unroll 8
        for (int k = 0; k < 64; k++) {
            float xv = __ldg(&x[k]);
#pragma unroll
            for (int v = 0; v < 4; v++) {
                float4 s4 = *(const float4*)&sv[v][k * 4];
                a[v][0] += xv * s4.x; a[v][1] += xv * s4.y;
                a[v][2] += xv * s4.z; a[v][3] += xv * s4.w;
            }
        }
        *(float4*)&el[(size_t)(e0)     * MAXN * 4 + (size_t)i * 4] = make_float4(a[0][0], a[0][1], a[0][2], a[0][3]);
        *(float4*)&el[(size_t)(e0 + 2) * MAXN * 4 + (size_t)i * 4] = make_float4(a[1][0], a[1][1], a[1][2], a[1][3]);
        *(float4*)&er[(size_t)(r0)     * MAXN * 4 + (size_t)i * 4] = make_float4(a[2][0], a[2][1], a[2][2], a[2][3]);
        *(float4*)&er[(size_t)(r0 + 2) * MAXN * 4 + (size_t)i * 4] = make_float4(a[3][0], a[3][1], a[3][2], a[3][3]);
    }

    // warp-reduce max of the 8 el values, lane0 atomicMax into elmax[rel*4+h]
    float mv[8];
#pragma unroll
    for (int j = 0; j < 4; j++) { mv[j] = a[0][j]; mv[4 + j] = a[1][j]; }
#pragma unroll
    for (int o = 16; o; o >>= 1)
#pragma unroll
        for (int j = 0; j < 8; j++)
            mv[j] = fmaxf(mv[j], __shfl_xor_sync(0xffffffffu, mv[j], o));
    if ((threadIdx.x & 31) == 0) {
#pragma unroll
        for (int j = 0; j < 4; j++) {
            atomicMax(&elmax[(e0)     * 4 + j], fenc(mv[j]));
            atomicMax(&elmax[(e0 + 2) * 4 + j], fenc(mv[4 + j]));
        }
    }
}

// ---------------- CSR build ----------------
__global__ void hist_kernel(const int* __restrict__ edges, int* __restrict__ cnt, int E, int n)
{
    for (int idx = blockIdx.x * blockDim.x + threadIdx.x; idx < 4 * E; idx += gridDim.x * blockDim.x) {
        int r = idx / E, i = idx - r * E;
        int dst = edges[(size_t)(2 * r + 1) * E + i];
        atomicAdd(&cnt[r * n + dst], 1);
    }
}

__global__ void scan_kernel(int* __restrict__ cnt, int* __restrict__ rp, int n)
{
    int r = blockIdx.x;
    int t = threadIdx.x;
    int C = (n + 1023) / 1024;
    __shared__ int sums[1024];
    int base = t * C;
    int loc = 0;
    for (int i = 0; i < C; i++) {
        int idx = base + i;
        if (idx < n) loc += cnt[r * n + idx];
    }
    sums[t] = loc;
    __syncthreads();
    for (int off = 1; off < 1024; off <<= 1) {
        int v = (t >= off) ? sums[t - off] : 0;
        __syncthreads();
        sums[t] += v;
        __syncthreads();
    }
    int run = (t == 0) ? 0 : sums[t - 1];
    for (int i = 0; i < C; i++) {
        int idx = base + i;
        if (idx < n) {
            rp[(size_t)r * (n + 1) + idx] = run;
            run += cnt[r * n + idx];
        }
    }
    if (t == 1023) rp[(size_t)r * (n + 1) + n] = sums[1023];
    for (int i = 0; i < C; i++) {
        int idx = base + i;
        if (idx < n) cnt[r * n + idx] = 0;
    }
}

__global__ void scatter_kernel(const int* __restrict__ edges, int* __restrict__ cnt,
                               const int* __restrict__ rp, int* __restrict__ col, int E, int n)
{
    for (int idx = blockIdx.x * blockDim.x + threadIdx.x; idx < 4 * E; idx += gridDim.x * blockDim.x) {
        int r = idx / E, i = idx - r * E;
        int src = edges[(size_t)(2 * r) * E + i];
        int dst = edges[(size_t)(2 * r + 1) * E + i];
        int pos = rp[(size_t)r * (n + 1) + dst] + atomicAdd(&cnt[r * n + dst], 1);
        col[(size_t)r * E + pos] = src;
    }
}

// ---------------- GAT aggregation: single fused pass (global-max-shifted softmax) -----------
__device__ __forceinline__ float lrelu(float x) { return x > 0.f ? x : 0.2f * x; }

__global__ void gat_agg_kernel(float* __restrict__ aggT, float* __restrict__ aggW,
                               const float* __restrict__ Xt, const float* __restrict__ Xw,
                               const float* __restrict__ el, const float* __restrict__ er,
                               const unsigned* __restrict__ elmax,
                               const int* __restrict__ rp, const int* __restrict__ col,
                               int NT, int NW, int E)
{
    const size_t EO4 = (size_t)MAXN * 4;
    int yt = blockIdx.y;
    int n = yt ? NW : NT;
    float* agg = yt ? aggW : aggT;
    const float* X = yt ? Xt : Xw;
    int ra = yt, rb = yt + 2;

    int w = (blockIdx.x * blockDim.x + threadIdx.x) >> 5;
    int lane = threadIdx.x & 31;
    if (w >= n) return;

    const int h  = lane >> 3;
    const int dq = (lane & 7) * 2;

    float4 acc[2][2];
#pragma unroll
    for (int q = 0; q < 2; q++) {
        acc[q][0] = make_float4(0.f, 0.f, 0.f, 0.f);
        acc[q][1] = make_float4(0.f, 0.f, 0.f, 0.f);
    }

#pragma unroll
    for (int q = 0; q < 2; q++) {
        int rel = q ? rb : ra;
        const float* elr = el + (size_t)rel * EO4;
        const float* err = er + (size_t)rel * EO4;
        const int* rpr   = rp + (size_t)rel * (MAXN + 1);
        const int* colr  = col + (size_t)rel * E;

        int s0 = rpr[w], s1 = rpr[w + 1];
        if (s1 <= s0) continue;

        float4 e4 = *(const float4*)(err + (size_t)w * 4);
        float erh = (h < 2) ? ((h == 0) ? e4.x : e4.y) : ((h == 2) ? e4.z : e4.w);
        // shift = lrelu(global el max + er) >= per-dst max score (lrelu monotone); exact softmax
        float mh = lrelu(fdec(elmax[rel * 4 + h]) + erh);
        float zh = 0.f;

        int e = s0;
        for (; e + 1 < s1; e += 2) {
            int sA = colr[e], sB = colr[e + 1];
            float4 lA = *(const float4*)(elr + (size_t)sA * 4);
            float4 lB = *(const float4*)(elr + (size_t)sB * 4);
            const float4* xa = (const float4*)(X + (size_t)sA * 64);
            const float4* xb = (const float4*)(X + (size_t)sB * 64);
            float4 xa0 = xa[dq], xa1 = xa[dq + 1];
            float4 xb0 = xb[dq], xb1 = xb[dq + 1];
            float lvA = (h < 2) ? ((h == 0) ? lA.x : lA.y) : ((h == 2) ? lA.z : lA.w);
            float lvB = (h < 2) ? ((h == 0) ? lB.x : lB.y) : ((h == 2) ? lB.z : lB.w);
            float aA = __expf(lrelu(lvA + erh) - mh);
            float aB = __expf(lrelu(lvB + erh) - mh);
            zh += aA + aB;
            acc[q][0].x = fmaf(aA, xa0.x, acc[q][0].x);
            acc[q][0].y = fmaf(aA, xa0.y, acc[q][0].y);
            acc[q][0].z = fmaf(aA, xa0.z, acc[q][0].z);
            acc[q][0].w = fmaf(aA, xa0.w, acc[q][0].w);
            acc[q][1].x = fmaf(aA, xa1.x, acc[q][1].x);
            acc[q][1].y = fmaf(aA, xa1.y, acc[q][1].y);
            acc[q][1].z = fmaf(aA, xa1.z, acc[q][1].z);
            acc[q][1].w = fmaf(aA, xa1.w, acc[q][1].w);
            acc[q][0].x = fmaf(aB, xb0.x, acc[q][0].x);
            acc[q][0].y = fmaf(aB, xb0.y, acc[q][0].y);
            acc[q][0].z = fmaf(aB, xb0.z, acc[q][0].z);
            acc[q][0].w = fmaf(aB, xb0.w, acc[q][0].w);
            acc[q][1].x = fmaf(aB, xb1.x, acc[q][1].x);
            acc[q][1].y = fmaf(aB, xb1.y, acc[q][1].y);
            acc[q][1].z = fmaf(aB, xb1.z, acc[q][1].z);
            acc[q][1].w = fmaf(aB, xb1.w, acc[q][1].w);
        }
        if (e < s1) {
            int s = colr[e];
            float4 l4 = *(const float4*)(elr + (size_t)s * 4);
            float lv = (h < 2) ? ((h == 0) ? l4.x : l4.y) : ((h == 2) ? l4.z : l4.w);
            float ah = __expf(lrelu(lv + erh) - mh);
            const float4* xp = (const float4*)(X + (size_t)s * 64);
            float4 x0 = xp[dq], x1 = xp[dq + 1];
            zh += ah;
            acc[q][0].x = fmaf(ah, x0.x, acc[q][0].x);
            acc[q][0].y = fmaf(ah, x0.y, acc[q][0].y);
            acc[q][0].z = fmaf(ah, x0.z, acc[q][0].z);
            acc[q][0].w = fmaf(ah, x0.w, acc[q][0].w);
            acc[q][1].x = fmaf(ah, x1.x, acc[q][1].x);
            acc[q][1].y = fmaf(ah, x1.y, acc[q][1].y);
            acc[q][1].z = fmaf(ah, x1.z, acc[q][1].z);
            acc[q][1].w = fmaf(ah, x1.w, acc[q][1].w);
        }

        float ih = (zh > 0.f) ? (1.f / zh) : 0.f;
        acc[q][0].x *= ih; acc[q][0].y *= ih; acc[q][0].z *= ih; acc[q][0].w *= ih;
        acc[q][1].x *= ih; acc[q][1].y *= ih; acc[q][1].z *= ih; acc[q][1].w *= ih;
    }

    float4* op = (float4*)(agg + (size_t)w * 512);
    int base = h * 16 + (lane & 7) * 2;
    op[base]           = acc[0][0];
    op[base + 1]       = acc[0][1];
    op[64 + base]      = acc[1][0];
    op[64 + base + 1]  = acc[1][1];
}

// ------------- SAGE1 combine, both types via blockIdx.y -------------
__global__ void sage1_combine_kernel(float* __restrict__ t0, float* __restrict__ w0,
    const float* __restrict__ Zt, const float* __restrict__ Zw,
    const int* __restrict__ rp, const int* __restrict__ col,
    int NT, int NW, int E)
{
    int typ = blockIdx.y;
    float* X = typ ? w0 : t0;
    const float* Zself = typ ? Zw : Zt;
    const float* Zsrc  = typ ? Zt : Zw;
    int n = typ ? NW : NT;
    const int* rpa  = rp + (size_t)(typ)     * (MAXN + 1);
    const int* cola = col + (size_t)(typ)     * E;
    const int* rpb  = rp + (size_t)(typ + 2) * (MAXN + 1);
    const int* colb = col + (size_t)(typ + 2) * E;

    int w = (blockIdx.x * blockDim.x + threadIdx.x) >> 5;
    int lane = threadIdx.x & 31;
    if (w >= n) return;
    float mx = 0.f, my = 0.f;
    {
        int s0 = rpa[w], s1 = rpa[w + 1];
        float sx = 0.f, sy = 0.f;
        for (int e = s0; e < s1; e++) {
            int s = cola[e];
            float2 v = *(const float2*)&Zsrc[(size_t)s * 192 + 64 + lane * 2];
            sx += v.x; sy += v.y;
        }
        float inv = 1.f / fmaxf((float)(s1 - s0), 1.f);
        mx += sx * inv; my += sy * inv;
    }
    {
        int s0 = rpb[w], s1 = rpb[w + 1];
        float sx = 0.f, sy = 0.f;
        for (int e = s0; e < s1; e++) {
            int s = colb[e];
            float2 v = *(const float2*)&Zsrc[(size_t)s * 192 + 128 + lane * 2];
            sx += v.x; sy += v.y;
        }
        float inv = 1.f / fmaxf((float)(s1 - s0), 1.f);
        mx += sx * inv; my += sy * inv;
    }
    float2 sv = *(const float2*)&Zself[(size_t)w * 192 + lane * 2];
    float2 o;
    o.x = fmaxf(sv.x + mx, 0.f);
    o.y = fmaxf(sv.y + my, 0.f);
    *(float2*)&X[(size_t)w * 64 + lane * 2] = o;
}

// ------------- SAGE2 projections, both types via blockIdx.y -------------
__global__ void proj6_kernel(const float* __restrict__ t1, const float* __restrict__ w1,
    const float* __restrict__ Ws, const float* __restrict__ Wn,
    float* __restrict__ el, float* __restrict__ er, int NT, int NW)
{
    const size_t Y2 = (size_t)MAXN * 2;
    int typ = blockIdx.y;
    const float* X = typ ? w1 : t1;
    int n = typ ? NW : NT;
    const float* WsA = Ws + (typ ? 1 : 0) * 512;
    const float* WsB = Ws + (typ ? 3 : 2) * 512;
    const float* WnA = Wn + (typ ? 0 : 1) * 512;
    const float* WnB = Wn + (typ ? 2 : 3) * 512;
    float* selfO = er + (size_t)typ * Y2;
    float* yA = el + (size_t)(typ ? 0 : 1) * Y2;
    float* yB = el + (size_t)(typ ? 2 : 3) * Y2;

    __shared__ float sw[3][512];
    for (int i = threadIdx.x; i < 512; i += blockDim.x) {
        sw[0][i] = WsA[i] + WsB[i];
        sw[1][i] = WnA[i];
        sw[2][i] = WnB[i];
    }
    __syncthreads();
    int w = (blockIdx.x * blockDim.x + threadIdx.x) >> 5;
    int lane = threadIdx.x & 31;
    if (w >= n) return;
    float a[6] = {0.f, 0.f, 0.f, 0.f, 0.f, 0.f};
    for (int k = lane; k < 256; k += 32) {
        float x = X[(size_t)w * 256 + k];
        a[0] += x * sw[0][2 * k]; a[1] += x * sw[0][2 * k + 1];
        a[2] += x * sw[1][2 * k]; a[3] += x * sw[1][2 * k + 1];
        a[4] += x * sw[2][2 * k]; a[5] += x * sw[2][2 * k + 1];
    }
#pragma unroll
    for (int o = 16; o; o >>= 1)
#pragma unroll
        for (int j = 0; j < 6; j++)
            a[j] += __shfl_xor_sync(0xffffffffu, a[j], o);
    if (lane == 0) {
        *(float2*)&selfO[(size_t)w * 2] = make_float2(a[0], a[1]);
        *(float2*)&yA[(size_t)w * 2]    = make_float2(a[2], a[3]);
        *(float2*)&yB[(size_t)w * 2]    = make_float2(a[4], a[5]);
    }
}

// ------------- SAGE2 combine, both types via blockIdx.y -------------
__global__ void sage2_combine_kernel(float* __restrict__ fout,
    const float* __restrict__ el, const float* __restrict__ er,
    const int* __restrict__ rp, const int* __restrict__ col,
    const float* __restrict__ b, int NT, int NW, int E)
{
    const size_t Y2 = (size_t)MAXN * 2;
    int typ = blockIdx.y;
    int n = typ ? NW : NT;
    float* out = fout + (typ ? (size_t)NT * 2 : 0);
    const float* selfO = er + (size_t)typ * Y2;
    const float* yA = el + (size_t)(typ)     * Y2;
    const float* yB = el + (size_t)(typ + 2) * Y2;
    const int* rpa  = rp + (size_t)(typ)     * (MAXN + 1);
    const int* cola = col + (size_t)(typ)     * E;
    const int* rpb  = rp + (size_t)(typ + 2) * (MAXN + 1);
    const int* colb = col + (size_t)(typ + 2) * E;
    const float* bA = b + typ * 2;
    const float* bB = b + (typ + 2) * 2;

    int w = blockIdx.x * blockDim.x + threadIdx.x;
    if (w >= n) return;
    float2 r = *(const float2*)&selfO[(size_t)w * 2];
    r.x += bA[0] + bB[0];
    r.y += bA[1] + bB[1];
    {
        int s0 = rpa[w], s1 = rpa[w + 1];
        float sx = 0.f, sy = 0.f;
        for (int e = s0; e < s1; e++) {
            float2 v = *(const float2*)&yA[(size_t)cola[e] * 2];
            sx += v.x; sy += v.y;
        }
        float inv = 1.f / fmaxf((float)(s1 - s0), 1.f);
        r.x += sx * inv; r.y += sy * inv;
    }
    {
        int s0 = rpb[w], s1 = rpb[w + 1];
        float sx = 0.f, sy = 0.f;
        for (int e = s0; e < s1; e++) {
            float2 v = *(const float2*)&yB[(size_t)colb[e] * 2];
            sx += v.x; sy += v.y;
        }
        float inv = 1.f / fmaxf((float)(s1 - s0), 1.f);
        r.x += sx * inv; r.y += sy * inv;
    }
    *(float2*)&out[(size_t)w * 2] = r;
}

// ---------------- host helpers ----------------
static void gemm_bs(const float* A, const __nv_bfloat16* Bh, const __nv_bfloat16* Bl, float* C,
                    const float* bias, int M, int N, int K, int relu, cudaStream_t st = 0)
{
    dim3 g(N / 64, (M + 127) / 128);
    if ((K & 15) == 0) gemm_bs_kernel<true><<<g, 256, 0, st>>>(A, Bh, Bl, C, bias, M, N, K, relu);
    else               gemm_bs_kernel<false><<<g, 256, 0, st>>>(A, Bh, Bl, C, bias, M, N, K, relu);
}

extern "C" void kernel_launch(void* const* d_in, const int* in_sizes, int n_in,
                              void* d_out, int out_size)
{
    const float* tx_feat  = (const float*)d_in[0];
    const float* w_feat   = (const float*)d_in[1];
    const int*   edges    = (const int*)d_in[2];
    const float* tx_W     = (const float*)d_in[3];
    const float* tx_b     = (const float*)d_in[4];
    const float* w_W      = (const float*)d_in[5];
    const float* w_b      = (const float*)d_in[6];
    const float* gat1_W   = (const float*)d_in[7];
    const float* gat1_al  = (const float*)d_in[8];
    const float* gat1_ar  = (const float*)d_in[9];
    const float* gat1_b   = (const float*)d_in[10];
    const float* sage1_Ws = (const float*)d_in[11];
    const float* sage1_Wn = (const float*)d_in[12];
    const float* sage1_b  = (const float*)d_in[13];
    const float* gat2_W   = (const float*)d_in[14];
    const float* gat2_al  = (const float*)d_in[15];
    const float* gat2_ar  = (const float*)d_in[16];
    const float* gat2_b   = (const float*)d_in[17];
    const float* sage2_Ws = (const float*)d_in[18];
    const float* sage2_Wn = (const float*)d_in[19];
    const float* sage2_b  = (const float*)d_in[20];

    int NT = in_sizes[0] / 166;
    int NW = in_sizes[1] / 56;
    int E  = in_sizes[2] / 8;
    if (NT > MAXN) NT = MAXN;
    if (NW > MAXN) NW = MAXN;
    if (E > MAXE) E = MAXE;

    float *t0, *w0, *t1, *w1, *hs, *el, *er, *alv, *arv, *bsum, *gbias;
    unsigned* elmax;
    __nv_bfloat16 *bh, *bl;
    int *cnt, *rp, *col;
    cudaGetSymbolAddress((void**)&t0, d_t0);
    cudaGetSymbolAddress((void**)&w0, d_w0);
    cudaGetSymbolAddress((void**)&t1, d_t1);
    cudaGetSymbolAddress((void**)&w1, d_w1);
    cudaGetSymbolAddress((void**)&hs, d_hs);
    cudaGetSymbolAddress((void**)&el, d_el);
    cudaGetSymbolAddress((void**)&er, d_er);
    cudaGetSymbolAddress((void**)&alv, d_alv);
    cudaGetSymbolAddress((void**)&arv, d_arv);
    cudaGetSymbolAddress((void**)&elmax, d_elmax);
    cudaGetSymbolAddress((void**)&bh, d_bh16);
    cudaGetSymbolAddress((void**)&bl, d_bl16);
    cudaGetSymbolAddress((void**)&bsum, d_bsum);
    cudaGetSymbolAddress((void**)&gbias, d_gbias);
    cudaGetSymbolAddress((void**)&cnt, d_cnt);
    cudaGetSymbolAddress((void**)&rp, d_rpv);
    cudaGetSymbolAddress((void**)&col, d_colv);

    float* fout = (float*)d_out;
    float* aggT = hs;
    float* aggW = hs + (size_t)MAXN * 512;
    float* Zt = hs;
    float* Zw = hs + (size_t)MAXN * 512;
    int nmax = NT > NW ? NT : NW;

    // ---- one-time stream/event setup (first call is not graph-captured) ----
    static cudaStream_t s2 = nullptr, s3 = nullptr;
    static cudaEvent_t evFork = nullptr, evJoin = nullptr, evSplit = nullptr, evS3 = nullptr;
    if (!s2) {
        cudaStreamCreateWithFlags(&s2, cudaStreamNonBlocking);
        cudaStreamCreateWithFlags(&s3, cudaStreamNonBlocking);
        cudaEventCreateWithFlags(&evFork, cudaEventDisableTiming);
        cudaEventCreateWithFlags(&evJoin, cudaEventDisableTiming);
        cudaEventCreateWithFlags(&evSplit, cudaEventDisableTiming);
        cudaEventCreateWithFlags(&evS3, cudaEventDisableTiming);
    }

    // ---- fork ----
    cudaEventRecord(evFork, 0);
    cudaStreamWaitEvent(s2, evFork, 0);
    cudaStreamWaitEvent(s3, evFork, 0);

    // s2: CSR build (edges only)
    cudaMemsetAsync(cnt, 0, 4 * (size_t)MAXN * sizeof(int), s2);
    hist_kernel<<<(4 * E + 255) / 256, 256, 0, s2>>>(edges, cnt, E, NT);
    scan_kernel<<<4, 1024, 0, s2>>>(cnt, rp, NT);
    scatter_kernel<<<(4 * E + 255) / 256, 256, 0, s2>>>(edges, cnt, rp, col, E, NT);
    cudaEventRecord(evJoin, s2);

    // s3: all weight packs (weights only), then w input projection
    pack_gatout_kernel<<<265, 256, 0, s3>>>(gat1_W, gat1_b, gat1_al, gat1_ar,
                                            bh + G1OFF, bl + G1OFF, gbias, alv, arv, elmax);
    pack_gatout_kernel<<<265, 256, 0, s3>>>(gat2_W, gat2_b, gat2_al, gat2_ar,
                                            bh + G2OFF, bl + G2OFF, gbias + 512,
                                            alv + 1024, arv + 1024, elmax + 16);
    pack_sage1_kernel<<<384, 256, 0, s3>>>(sage1_Ws, sage1_Wn, sage1_b,
                                           bh + S1OFF, bl + S1OFF, bsum);

    // main: input weight split, then t projection; w projection on s3
    split_plain2_kernel<<<(166 * 64 + 56 * 64 + 255) / 256, 256>>>(
        tx_W, 166 * 64, w_W, 56 * 64, 166 * 64, bh + INOFF, bl + INOFF);
    cudaEventRecord(evSplit, 0);
    cudaStreamWaitEvent(s3, evSplit, 0);
    gemm_bs(w_feat, bh + INOFF + 166 * 64, bl + INOFF + 166 * 64, w0, w_b, NW, 64, 56, 1, s3);
    cudaEventRecord(evS3, s3);

    gemm_bs(tx_feat, bh + INOFF, bl + INOFF, t0, tx_b, NT, 64, 166, 1);

    // join s3 (w0 + all packs ready), then GAT1 el/er projection
    cudaStreamWaitEvent(0, evS3, 0);
    {
        dim3 gv((nmax + 255) / 256, 2);
        vecproj_fused_kernel<<<gv, 256>>>(t0, w0, alv, arv, el, er, elmax, NT, NW);
    }

    // join s2 (CSR ready), then edge-dependent work
    cudaStreamWaitEvent(0, evJoin, 0);
    {
        dim3 ga((nmax + 7) / 8, 2);
        gat_agg_kernel<<<ga, 256>>>(aggT, aggW, t0, w0, el, er, elmax, rp, col, NT, NW, E);
        gemm_gat_kernel<<<dim3(4, (nmax + 127) / 128, 2), 256>>>(aggT, aggW, bh + G1OFF, bl + G1OFF,
                                                                 t1, w1, gbias, NT, NW);
    }

    // ---- S2: hetero SAGE1 (256 -> 64): one fused N=192 GEMM per type ----
    {
        gemm_bs(t1, bh + S1OFF,         bl + S1OFF,         Zt, bsum,       NT, 192, 256, 0);
        gemm_bs(w1, bh + S1OFF + 49152, bl + S1OFF + 49152, Zw, bsum + 192, NW, 192, 256, 0);
        dim3 gc((nmax + 7) / 8, 2);
        sage1_combine_kernel<<<gc, 256>>>(t0, w0, Zt, Zw, rp, col, NT, NW, E);
    }

    // ---- S3: hetero GAT2 (64 -> 256): aggregate-then-project (weights pre-packed) ----
    {
        dim3 gv((nmax + 255) / 256, 2);
        vecproj_fused_kernel<<<gv, 256>>>(t0, w0, alv + 1024, arv + 1024, el, er,
                                          elmax + 16, NT, NW);
        dim3 ga((nmax + 7) / 8, 2);
        gat_agg_kernel<<<ga, 256>>>(aggT, aggW, t0, w0, el, er, elmax + 16, rp, col, NT, NW, E);
        gemm_gat_kernel<<<dim3(4, (nmax + 127) / 128, 2), 256>>>(aggT, aggW, bh + G2OFF, bl + G2OFF,
                                                                 t1, w1, gbias + 512, NT, NW);
    }

    // ---- S4: hetero SAGE2 (256 -> 2): project-then-aggregate ----
    {
        dim3 gp((nmax + 7) / 8, 2);
        proj6_kernel<<<gp, 256>>>(t1, w1, sage2_Ws, sage2_Wn, el, er, NT, NW);
        dim3 gs((nmax + 255) / 256, 2);
        sage2_combine_kernel<<<gs, 256>>>(fout, el, er, rp, col, sage2_b, NT, NW, E);
    }
}